// round 15
// baseline (speedup 1.0000x reference)
#include <cuda_runtime.h>
#include <cstdint>

// ---------------- scratch (device globals) ----------------------------------
#define MAXN 50176   // padded 50000
#define MAXE 1048576
__device__ float g_h  [MAXN * 128];
__device__ float g_pool[256 * 128 + 256];   // [0,32768) pool sums, [32768,) cnt
__device__ int   g_deg [MAXN + 1];
__device__ int   g_off [MAXN + 1];
__device__ int   g_cur [MAXN];
__device__ int   g_adj [MAXE];

// ---------------- zero -------------------------------------------------------
__global__ void zero_kernel(float* __restrict__ p, int n4) {
    int i = blockIdx.x * blockDim.x + threadIdx.x;
    if (i < n4) ((float4*)p)[i] = make_float4(0.f, 0.f, 0.f, 0.f);
}

// ---------------- CSR build --------------------------------------------------
__global__ void count_kernel(const int* __restrict__ dst, int* __restrict__ deg, int E) {
    int e = blockIdx.x * blockDim.x + threadIdx.x;
    if (e < E) atomicAdd(deg + __ldg(dst + e), 1);
}

__global__ void scan_kernel(const int* __restrict__ deg, int* __restrict__ off,
                            int* __restrict__ cur, int N) {
    __shared__ int part[1024];
    const int tid = threadIdx.x;
    const int seg = (N + 1023) / 1024;
    const int start = tid * seg;
    const int end = min(start + seg, N);
    int s = 0;
    for (int i = start; i < end; i++) s += deg[i];
    part[tid] = s;
    __syncthreads();
    int v = s;
#pragma unroll
    for (int d = 1; d < 1024; d <<= 1) {
        int t = (tid >= d) ? part[tid - d] : 0;
        __syncthreads();
        part[tid] += t;
        __syncthreads();
    }
    int run = part[tid] - v;
    for (int i = start; i < end; i++) {
        off[i] = run; cur[i] = run;
        run += deg[i];
    }
    if (end == N) off[N] = run;
}

__global__ void fill_kernel(const int* __restrict__ src, const int* __restrict__ dst,
                            int* __restrict__ cur, int* __restrict__ adj,
                            int* __restrict__ deg, int E) {
    int e = blockIdx.x * blockDim.x + threadIdx.x;
    if (e < E) {
        int p = atomicAdd(cur + __ldg(dst + e), 1);
        adj[p] = __ldg(src + e);
    }
    if (e <= MAXN) deg[e] = 0;   // reset for next replay
}

__global__ void cnt_kernel(const int* __restrict__ batch, float* __restrict__ cnt, int N) {
    int i = blockIdx.x * blockDim.x + threadIdx.x;
    if (i < N) atomicAdd(cnt + __ldg(batch + i), 1.0f);
}

// ---------------- persistent warp-specialized fused GIN layer ----------------
#define AS 132                 // Atile row stride (floats)
#define TROWS 176              // 22 row-groups x 16 col-groups = 352 consumer thr
#define NSM 148
#define NCONS 352              // 11 consumer warps; 5 producer warps
#define TK 32
#define SMEM_BYTES ((2 * TROWS * AS + 2 * TK * 128) * 4)
#define CONS_BAR() asm volatile("bar.sync 1, 352;" ::: "memory")

__device__ __forceinline__ void stage_w(const float* __restrict__ W, float* __restrict__ Wsm,
                                        int k0, int tid) {
    for (int ch = tid; ch < 1024; ch += NCONS) {   // 32 rows x 32 float4
        int r = ch >> 5, c4 = ch & 31;
        const float* g = W + (size_t)(k0 + r) * 128 + c4 * 4;
        unsigned sm = (unsigned)__cvta_generic_to_shared(Wsm + r * 128 + c4 * 4);
        asm volatile("cp.async.cg.shared.global [%0], [%1], 16;" :: "r"(sm), "l"(g));
    }
    asm volatile("cp.async.commit_group;");
}

// pipelined gather: Abuf[row] = X[node] + sum_{j in adj(node)} X[j]
__device__ __forceinline__ void gather_rows(const float* __restrict__ X,
                                            const int* __restrict__ adj,
                                            const int* __restrict__ off,
                                            float* __restrict__ Abuf,
                                            int row0, int N, int warp, int nwarps, int lane) {
    for (int row = warp; row < TROWS; row += nwarps) {
        int node = row0 + row;
        float4 a0 = make_float4(0.f, 0.f, 0.f, 0.f);
        float4 a1 = a0, a2 = a0, a3 = a0;
        if (node < N) {
            a0 = __ldg(((const float4*)(X + (size_t)node * 128)) + lane);
            const int start = __ldg(off + node);
            const int d = __ldg(off + node + 1) - start;
            const int* ap = adj + start;
            int j = 0;
            int n0 = 0, n1 = 0, n2 = 0, n3 = 0;
            if (d >= 4) {
                n0 = __ldg(ap + 0); n1 = __ldg(ap + 1);
                n2 = __ldg(ap + 2); n3 = __ldg(ap + 3);
            }
            for (; j + 8 <= d; j += 4) {
                float4 v0 = __ldg(((const float4*)(X + (size_t)n0 * 128)) + lane);
                float4 v1 = __ldg(((const float4*)(X + (size_t)n1 * 128)) + lane);
                float4 v2 = __ldg(((const float4*)(X + (size_t)n2 * 128)) + lane);
                float4 v3 = __ldg(((const float4*)(X + (size_t)n3 * 128)) + lane);
                n0 = __ldg(ap + j + 4); n1 = __ldg(ap + j + 5);
                n2 = __ldg(ap + j + 6); n3 = __ldg(ap + j + 7);
                a0.x += v0.x; a0.y += v0.y; a0.z += v0.z; a0.w += v0.w;
                a1.x += v1.x; a1.y += v1.y; a1.z += v1.z; a1.w += v1.w;
                a2.x += v2.x; a2.y += v2.y; a2.z += v2.z; a2.w += v2.w;
                a3.x += v3.x; a3.y += v3.y; a3.z += v3.z; a3.w += v3.w;
            }
            if (j + 4 <= d) {
                float4 v0 = __ldg(((const float4*)(X + (size_t)n0 * 128)) + lane);
                float4 v1 = __ldg(((const float4*)(X + (size_t)n1 * 128)) + lane);
                float4 v2 = __ldg(((const float4*)(X + (size_t)n2 * 128)) + lane);
                float4 v3 = __ldg(((const float4*)(X + (size_t)n3 * 128)) + lane);
                a0.x += v0.x; a0.y += v0.y; a0.z += v0.z; a0.w += v0.w;
                a1.x += v1.x; a1.y += v1.y; a1.z += v1.z; a1.w += v1.w;
                a2.x += v2.x; a2.y += v2.y; a2.z += v2.z; a2.w += v2.w;
                a3.x += v3.x; a3.y += v3.y; a3.z += v3.z; a3.w += v3.w;
                j += 4;
            }
            for (; j < d; j++) {
                int n = __ldg(ap + j);
                float4 v = __ldg(((const float4*)(X + (size_t)n * 128)) + lane);
                a0.x += v.x; a0.y += v.y; a0.z += v.z; a0.w += v.w;
            }
            a0.x += a1.x + a2.x + a3.x;
            a0.y += a1.y + a2.y + a3.y;
            a0.z += a1.z + a2.z + a3.z;
            a0.w += a1.w + a2.w + a3.w;
        }
        *(float4*)&Abuf[row * AS + lane * 4] = a0;
    }
}

__device__ __forceinline__ void gemm_from_atile(const float* __restrict__ Atile,
                                                const float* __restrict__ W,
                                                float* __restrict__ Ws,
                                                int tid, int rrow, int ccol,
                                                unsigned long long acc[8][4]) {
    stage_w(W, Ws, 0, tid);
    for (int s = 0; s < 128 / TK; s++) {
        if (s < 128 / TK - 1) {
            stage_w(W, Ws + ((s + 1) & 1) * (TK * 128), (s + 1) * TK, tid);
            asm volatile("cp.async.wait_group 1;");
        } else {
            asm volatile("cp.async.wait_group 0;");
        }
        CONS_BAR();
        const float* Wb = Ws + (s & 1) * (TK * 128);
#pragma unroll
        for (int k4l = 0; k4l < TK / 4; k4l++) {
            const int kg = s * TK + k4l * 4;
            float4 av[8];
#pragma unroll
            for (int i = 0; i < 8; i++)
                av[i] = *(const float4*)&Atile[(rrow + i) * AS + kg];
#pragma unroll
            for (int kk = 0; kk < 4; kk++) {
                const float* wrow = Wb + (k4l * 4 + kk) * 128 + ccol;
                ulonglong2 w01 = *(const ulonglong2*)wrow;
                ulonglong2 w23 = *(const ulonglong2*)(wrow + 4);
#pragma unroll
                for (int i = 0; i < 8; i++) {
                    float a = (kk == 0) ? av[i].x : (kk == 1) ? av[i].y
                            : (kk == 2) ? av[i].z : av[i].w;
                    unsigned long long a2;
                    asm("mov.b64 %0, {%1, %1};" : "=l"(a2) : "f"(a));
                    asm("fma.rn.f32x2 %0, %1, %2, %0;" : "+l"(acc[i][0]) : "l"(a2), "l"(w01.x));
                    asm("fma.rn.f32x2 %0, %1, %2, %0;" : "+l"(acc[i][1]) : "l"(a2), "l"(w01.y));
                    asm("fma.rn.f32x2 %0, %1, %2, %0;" : "+l"(acc[i][2]) : "l"(a2), "l"(w23.x));
                    asm("fma.rn.f32x2 %0, %1, %2, %0;" : "+l"(acc[i][3]) : "l"(a2), "l"(w23.y));
                }
            }
        }
        CONS_BAR();
    }
}

__device__ __forceinline__ void consumer_tile(float* __restrict__ Atile,
                                              float* __restrict__ Ws,
                                              const float* __restrict__ Wa, const float* __restrict__ ba,
                                              const float* __restrict__ Wb, const float* __restrict__ bbv,
                                              float* __restrict__ OUT,
                                              const int* __restrict__ batch, float* __restrict__ pool,
                                              int row0, int N, int mode,
                                              int tid, int rrow, int ccol) {
    unsigned long long acc[8][4];
#pragma unroll
    for (int i = 0; i < 8; i++)
#pragma unroll
        for (int j = 0; j < 4; j++) acc[i][j] = 0ull;

    gemm_from_atile(Atile, Wa, Ws, tid, rrow, ccol, acc);

    {   // epilogue1: relu+bias -> Atile
        float4 bv0 = __ldg((const float4*)(ba + ccol));
        float4 bv1 = __ldg((const float4*)(ba + ccol + 4));
        float bb[8] = {bv0.x, bv0.y, bv0.z, bv0.w, bv1.x, bv1.y, bv1.z, bv1.w};
#pragma unroll
        for (int i = 0; i < 8; i++) {
            float o[8];
#pragma unroll
            for (int j = 0; j < 4; j++) {
                float lo, hi;
                asm("mov.b64 {%0, %1}, %2;" : "=f"(lo), "=f"(hi) : "l"(acc[i][j]));
                o[2 * j]     = fmaxf(lo + bb[2 * j], 0.f);
                o[2 * j + 1] = fmaxf(hi + bb[2 * j + 1], 0.f);
                acc[i][j] = 0ull;
            }
            *(float4*)&Atile[(rrow + i) * AS + ccol]     = make_float4(o[0], o[1], o[2], o[3]);
            *(float4*)&Atile[(rrow + i) * AS + ccol + 4] = make_float4(o[4], o[5], o[6], o[7]);
        }
    }
    CONS_BAR();

    gemm_from_atile(Atile, Wb, Ws, tid, rrow, ccol, acc);

    {   // epilogue2
        float4 bv0 = __ldg((const float4*)(bbv + ccol));
        float4 bv1 = __ldg((const float4*)(bbv + ccol + 4));
        float bb[8] = {bv0.x, bv0.y, bv0.z, bv0.w, bv1.x, bv1.y, bv1.z, bv1.w};
#pragma unroll
        for (int i = 0; i < 8; i++) {
            int grow = row0 + rrow + i;
            if (grow < N) {
                float o[8];
#pragma unroll
                for (int j = 0; j < 4; j++) {
                    float lo, hi;
                    asm("mov.b64 {%0, %1}, %2;" : "=f"(lo), "=f"(hi) : "l"(acc[i][j]));
                    o[2 * j]     = lo + bb[2 * j];
                    o[2 * j + 1] = hi + bb[2 * j + 1];
                }
                if (mode == 0) {
                    *(float4*)(OUT + (size_t)grow * 128 + ccol)     = make_float4(o[0], o[1], o[2], o[3]);
                    *(float4*)(OUT + (size_t)grow * 128 + ccol + 4) = make_float4(o[4], o[5], o[6], o[7]);
                } else {
                    int g = __ldg(batch + grow);
                    float* p = pool + (size_t)g * 128 + ccol;
                    asm volatile("red.global.add.v4.f32 [%0], {%1, %2, %3, %4};"
                                 :: "l"(p), "f"(o[0]), "f"(o[1]), "f"(o[2]), "f"(o[3]) : "memory");
                    asm volatile("red.global.add.v4.f32 [%0], {%1, %2, %3, %4};"
                                 :: "l"(p + 4), "f"(o[4]), "f"(o[5]), "f"(o[6]), "f"(o[7]) : "memory");
                }
            }
        }
    }
}

__global__ __launch_bounds__(512, 1)
void fused_layer_kernel(const float* __restrict__ X,
                        const int* __restrict__ adj, const int* __restrict__ off,
                        const float* __restrict__ Wa, const float* __restrict__ ba,
                        const float* __restrict__ Wb, const float* __restrict__ bbv,
                        float* __restrict__ OUT,
                        const int* __restrict__ batch, float* __restrict__ pool,
                        int N, int mode) {
    extern __shared__ float sm[];
    float* Abuf0 = sm;
    float* Abuf1 = sm + TROWS * AS;
    float* Ws    = sm + 2 * TROWS * AS;

    const int tid = threadIdx.x, wid = tid >> 5, lane = tid & 31;
    const int bid = blockIdx.x;
    const int ntiles = (N + TROWS - 1) / TROWS;   // 285 for N=50000 -> <=2 per CTA
    const int nt = (ntiles - bid + NSM - 1) / NSM;
    if (nt <= 0) return;

    // consumer geometry (tid 0..351): 22 row-groups x 16 col-groups
    const int tx = tid & 15, ty = tid >> 4;
    const int rrow = ty * 8, ccol = tx * 8;

    // prologue: all 16 warps gather tile 0
    gather_rows(X, adj, off, Abuf0, bid * TROWS, N, wid, 16, lane);
    __syncthreads();

    for (int i = 0; i < nt; i++) {
        float* Ab = (i & 1) ? Abuf1 : Abuf0;
        int row0 = (bid + i * NSM) * TROWS;
        if (tid < NCONS) {
            consumer_tile(Ab, Ws, Wa, ba, Wb, bbv, OUT, batch, pool,
                          row0, N, mode, tid, rrow, ccol);
        } else {
            if (i + 1 < nt) {
                float* An = (i & 1) ? Abuf0 : Abuf1;
                gather_rows(X, adj, off, An, (bid + (i + 1) * NSM) * TROWS,
                            N, wid - 11, 5, lane);
            }
        }
        __syncthreads();
    }
}

// ---------------- head: out = (sums/cnt) @ Wl + bl --------------------------
__global__ void final_kernel(const float* __restrict__ sums, const float* __restrict__ cnt,
                             const float* __restrict__ Wl, const float* __restrict__ bl,
                             float* __restrict__ out) {
    int g = blockIdx.x;
    int o = threadIdx.x;  // 64 threads
    __shared__ float p[128];
    float c = fmaxf(__ldg(cnt + g), 1.0f);
    for (int k = threadIdx.x; k < 128; k += 64)
        p[k] = __ldg(sums + g * 128 + k) / c;
    __syncthreads();
    float acc = __ldg(bl + o);
#pragma unroll 16
    for (int k = 0; k < 128; k++)
        acc += p[k] * __ldg(Wl + k * 64 + o);
    out[g * 64 + o] = acc;
}

// ---------------- launch -----------------------------------------------------
extern "C" void kernel_launch(void* const* d_in, const int* in_sizes, int n_in,
                              void* d_out, int out_size) {
    const float* x     = (const float*)d_in[0];
    const int*   ei    = (const int*)  d_in[1];
    const int*   batch = (const int*)  d_in[2];
    const float* W1a = (const float*)d_in[3];
    const float* b1a = (const float*)d_in[4];
    const float* W1b = (const float*)d_in[5];
    const float* b1b = (const float*)d_in[6];
    const float* W2a = (const float*)d_in[7];
    const float* b2a = (const float*)d_in[8];
    const float* W2b = (const float*)d_in[9];
    const float* b2b = (const float*)d_in[10];
    const float* Wl  = (const float*)d_in[11];
    const float* bl  = (const float*)d_in[12];
    float* out = (float*)d_out;

    const int N = in_sizes[0] / 128;
    const int E = in_sizes[1] / 2;
    const int* src = ei;
    const int* dst = ei + E;

    float *h, *pool;
    int *deg, *off, *cur, *adj;
    cudaGetSymbolAddress((void**)&h,    g_h);
    cudaGetSymbolAddress((void**)&pool, g_pool);
    cudaGetSymbolAddress((void**)&deg,  g_deg);
    cudaGetSymbolAddress((void**)&off,  g_off);
    cudaGetSymbolAddress((void**)&cur,  g_cur);
    cudaGetSymbolAddress((void**)&adj,  g_adj);
    float* cnt = pool + 256 * 128;

    cudaFuncSetAttribute(fused_layer_kernel,
                         cudaFuncAttributeMaxDynamicSharedMemorySize, SMEM_BYTES);

    const int eblocks = (E + 255) / 256;
    const int nblocks = (N + 255) / 256;

    // ---- CSR build (deg zero at entry: zero-init / re-zeroed by fill) ----
    count_kernel<<<eblocks, 256>>>(dst, deg, E);                 // #1
    scan_kernel <<<1, 1024>>>(deg, off, cur, N);                 // #2
    fill_kernel <<<eblocks, 256>>>(src, dst, cur, adj, deg, E);  // #3

    // ---- layer 1 (launch #4 — ncu capture target) ----
    fused_layer_kernel<<<NSM, 512, SMEM_BYTES>>>(
        x, adj, off, W1a, b1a, W1b, b1b, h, batch, pool, N, 0);

    // ---- pool/cnt init + counts ----
    zero_kernel<<<33, 256>>>(pool, (256 * 128 + 256) / 4);       // #5
    cnt_kernel <<<nblocks, 256>>>(batch, cnt, N);                // #6

    // ---- layer 2: pool += MLP2(h + gather), fused ----
    fused_layer_kernel<<<NSM, 512, SMEM_BYTES>>>(
        h, adj, off, W2a, b2a, W2b, b2b, nullptr, batch, pool, N, 1);

    // ---- head ----
    final_kernel<<<256, 64>>>(pool, cnt, Wl, bl, out);
}

// round 16
// speedup vs baseline: 1.6614x; 1.6614x over previous
#include <cuda_runtime.h>
#include <cstdint>

// ---------------- scratch (device globals) ----------------------------------
#define MAXN 50176   // padded 50000
#define MAXE 1048576
__device__ float g_h  [MAXN * 128];
__device__ float g_pool[256 * 128 + 256];   // [0,32768) pool sums, [32768,) cnt
__device__ int   g_deg [MAXN + 1];
__device__ int   g_off [MAXN + 1];
__device__ int   g_cur [MAXN];
__device__ int   g_adj [MAXE];
__device__ int   g_tctr[2];                 // dynamic tile counters (layer 1 / 2)

// ---------------- zero -------------------------------------------------------
__global__ void zero_kernel(float* __restrict__ p, int n4) {
    int i = blockIdx.x * blockDim.x + threadIdx.x;
    if (i < n4) ((float4*)p)[i] = make_float4(0.f, 0.f, 0.f, 0.f);
}

// ---------------- CSR build --------------------------------------------------
__global__ void count_kernel(const int* __restrict__ dst, int* __restrict__ deg, int E) {
    int e = blockIdx.x * blockDim.x + threadIdx.x;
    if (e < E) atomicAdd(deg + __ldg(dst + e), 1);
}

__global__ void scan_kernel(const int* __restrict__ deg, int* __restrict__ off,
                            int* __restrict__ cur, int N) {
    __shared__ int part[1024];
    const int tid = threadIdx.x;
    const int seg = (N + 1023) / 1024;
    const int start = tid * seg;
    const int end = min(start + seg, N);
    int s = 0;
    for (int i = start; i < end; i++) s += deg[i];
    part[tid] = s;
    __syncthreads();
    int v = s;
#pragma unroll
    for (int d = 1; d < 1024; d <<= 1) {
        int t = (tid >= d) ? part[tid - d] : 0;
        __syncthreads();
        part[tid] += t;
        __syncthreads();
    }
    int run = part[tid] - v;
    for (int i = start; i < end; i++) {
        off[i] = run; cur[i] = run;
        run += deg[i];
    }
    if (end == N) off[N] = run;
}

__global__ void fill_kernel(const int* __restrict__ src, const int* __restrict__ dst,
                            int* __restrict__ cur, int* __restrict__ adj,
                            int* __restrict__ deg, int* __restrict__ tctr, int E) {
    int e = blockIdx.x * blockDim.x + threadIdx.x;
    if (e < E) {
        int p = atomicAdd(cur + __ldg(dst + e), 1);
        adj[p] = __ldg(src + e);
    }
    if (e <= MAXN) deg[e] = 0;   // reset for next replay
    if (e < 2) tctr[e] = 0;      // reset dynamic tile counters
}

__global__ void cnt_kernel(const int* __restrict__ batch, float* __restrict__ cnt, int N) {
    int i = blockIdx.x * blockDim.x + threadIdx.x;
    if (i < N) atomicAdd(cnt + __ldg(batch + i), 1.0f);
}

// ---------------- persistent warp-specialized fused GIN layer ----------------
#define AS 132                 // Atile row stride (floats)
#define TROWS 128
#define NSM 148
#define NCONS 256              // 8 consumer warps; 8 producer warps
#define TK 32
#define SMEM_BYTES ((2 * TROWS * AS + 2 * TK * 128) * 4 + 32)
#define CONS_BAR() asm volatile("bar.sync 1, 256;" ::: "memory")
#define PROD_BAR() asm volatile("bar.sync 2, 256;" ::: "memory")

__device__ __forceinline__ void stage_w(const float* __restrict__ W, float* __restrict__ Wsm,
                                        int k0, int tid) {
#pragma unroll
    for (int t = 0; t < 4; t++) {
        int ch = tid + t * NCONS;                // 0..1023: 32 rows x 32 float4
        int r = ch >> 5, c4 = ch & 31;
        const float* g = W + (size_t)(k0 + r) * 128 + c4 * 4;
        unsigned sm = (unsigned)__cvta_generic_to_shared(Wsm + r * 128 + c4 * 4);
        asm volatile("cp.async.cg.shared.global [%0], [%1], 16;" :: "r"(sm), "l"(g));
    }
    asm volatile("cp.async.commit_group;");
}

// pipelined gather: Abuf[row] = X[node] + sum_{j in adj(node)} X[j]
__device__ __forceinline__ void gather_rows(const float* __restrict__ X,
                                            const int* __restrict__ adj,
                                            const int* __restrict__ off,
                                            float* __restrict__ Abuf,
                                            int row0, int N, int warp, int nwarps, int lane) {
    for (int row = warp; row < TROWS; row += nwarps) {
        int node = row0 + row;
        float4 a0 = make_float4(0.f, 0.f, 0.f, 0.f);
        float4 a1 = a0, a2 = a0, a3 = a0;
        if (node < N) {
            a0 = __ldg(((const float4*)(X + (size_t)node * 128)) + lane);
            const int start = __ldg(off + node);
            const int d = __ldg(off + node + 1) - start;
            const int* ap = adj + start;
            int j = 0;
            int n0 = 0, n1 = 0, n2 = 0, n3 = 0;
            if (d >= 4) {
                n0 = __ldg(ap + 0); n1 = __ldg(ap + 1);
                n2 = __ldg(ap + 2); n3 = __ldg(ap + 3);
            }
            for (; j + 8 <= d; j += 4) {
                float4 v0 = __ldg(((const float4*)(X + (size_t)n0 * 128)) + lane);
                float4 v1 = __ldg(((const float4*)(X + (size_t)n1 * 128)) + lane);
                float4 v2 = __ldg(((const float4*)(X + (size_t)n2 * 128)) + lane);
                float4 v3 = __ldg(((const float4*)(X + (size_t)n3 * 128)) + lane);
                n0 = __ldg(ap + j + 4); n1 = __ldg(ap + j + 5);
                n2 = __ldg(ap + j + 6); n3 = __ldg(ap + j + 7);
                a0.x += v0.x; a0.y += v0.y; a0.z += v0.z; a0.w += v0.w;
                a1.x += v1.x; a1.y += v1.y; a1.z += v1.z; a1.w += v1.w;
                a2.x += v2.x; a2.y += v2.y; a2.z += v2.z; a2.w += v2.w;
                a3.x += v3.x; a3.y += v3.y; a3.z += v3.z; a3.w += v3.w;
            }
            if (j + 4 <= d) {
                float4 v0 = __ldg(((const float4*)(X + (size_t)n0 * 128)) + lane);
                float4 v1 = __ldg(((const float4*)(X + (size_t)n1 * 128)) + lane);
                float4 v2 = __ldg(((const float4*)(X + (size_t)n2 * 128)) + lane);
                float4 v3 = __ldg(((const float4*)(X + (size_t)n3 * 128)) + lane);
                a0.x += v0.x; a0.y += v0.y; a0.z += v0.z; a0.w += v0.w;
                a1.x += v1.x; a1.y += v1.y; a1.z += v1.z; a1.w += v1.w;
                a2.x += v2.x; a2.y += v2.y; a2.z += v2.z; a2.w += v2.w;
                a3.x += v3.x; a3.y += v3.y; a3.z += v3.z; a3.w += v3.w;
                j += 4;
            }
            for (; j < d; j++) {
                int n = __ldg(ap + j);
                float4 v = __ldg(((const float4*)(X + (size_t)n * 128)) + lane);
                a0.x += v.x; a0.y += v.y; a0.z += v.z; a0.w += v.w;
            }
            a0.x += a1.x + a2.x + a3.x;
            a0.y += a1.y + a2.y + a3.y;
            a0.z += a1.z + a2.z + a3.z;
            a0.w += a1.w + a2.w + a3.w;
        }
        *(float4*)&Abuf[row * AS + lane * 4] = a0;
    }
}

__device__ __forceinline__ void gemm_from_atile(const float* __restrict__ Atile,
                                                const float* __restrict__ W,
                                                float* __restrict__ Ws,
                                                int tid, int rrow, int ccol,
                                                unsigned long long acc[8][4]) {
    stage_w(W, Ws, 0, tid);
    for (int s = 0; s < 128 / TK; s++) {
        if (s < 128 / TK - 1) {
            stage_w(W, Ws + ((s + 1) & 1) * (TK * 128), (s + 1) * TK, tid);
            asm volatile("cp.async.wait_group 1;");
        } else {
            asm volatile("cp.async.wait_group 0;");
        }
        CONS_BAR();
        const float* Wb = Ws + (s & 1) * (TK * 128);
#pragma unroll
        for (int k4l = 0; k4l < TK / 4; k4l++) {
            const int kg = s * TK + k4l * 4;
            float4 av[8];
#pragma unroll
            for (int i = 0; i < 8; i++)
                av[i] = *(const float4*)&Atile[(rrow + i) * AS + kg];
#pragma unroll
            for (int kk = 0; kk < 4; kk++) {
                const float* wrow = Wb + (k4l * 4 + kk) * 128 + ccol;
                ulonglong2 w01 = *(const ulonglong2*)wrow;
                ulonglong2 w23 = *(const ulonglong2*)(wrow + 4);
#pragma unroll
                for (int i = 0; i < 8; i++) {
                    float a = (kk == 0) ? av[i].x : (kk == 1) ? av[i].y
                            : (kk == 2) ? av[i].z : av[i].w;
                    unsigned long long a2;
                    asm("mov.b64 %0, {%1, %1};" : "=l"(a2) : "f"(a));
                    asm("fma.rn.f32x2 %0, %1, %2, %0;" : "+l"(acc[i][0]) : "l"(a2), "l"(w01.x));
                    asm("fma.rn.f32x2 %0, %1, %2, %0;" : "+l"(acc[i][1]) : "l"(a2), "l"(w01.y));
                    asm("fma.rn.f32x2 %0, %1, %2, %0;" : "+l"(acc[i][2]) : "l"(a2), "l"(w23.x));
                    asm("fma.rn.f32x2 %0, %1, %2, %0;" : "+l"(acc[i][3]) : "l"(a2), "l"(w23.y));
                }
            }
        }
        CONS_BAR();
    }
}

__device__ __forceinline__ void consumer_tile(float* __restrict__ Atile,
                                              float* __restrict__ Ws,
                                              const float* __restrict__ Wa, const float* __restrict__ ba,
                                              const float* __restrict__ Wb, const float* __restrict__ bbv,
                                              float* __restrict__ OUT,
                                              const int* __restrict__ batch, float* __restrict__ pool,
                                              int row0, int N, int mode,
                                              int tid, int rrow, int ccol) {
    unsigned long long acc[8][4];
#pragma unroll
    for (int i = 0; i < 8; i++)
#pragma unroll
        for (int j = 0; j < 4; j++) acc[i][j] = 0ull;

    gemm_from_atile(Atile, Wa, Ws, tid, rrow, ccol, acc);

    {   // epilogue1: relu+bias -> Atile
        float4 bv0 = __ldg((const float4*)(ba + ccol));
        float4 bv1 = __ldg((const float4*)(ba + ccol + 4));
        float bb[8] = {bv0.x, bv0.y, bv0.z, bv0.w, bv1.x, bv1.y, bv1.z, bv1.w};
#pragma unroll
        for (int i = 0; i < 8; i++) {
            float o[8];
#pragma unroll
            for (int j = 0; j < 4; j++) {
                float lo, hi;
                asm("mov.b64 {%0, %1}, %2;" : "=f"(lo), "=f"(hi) : "l"(acc[i][j]));
                o[2 * j]     = fmaxf(lo + bb[2 * j], 0.f);
                o[2 * j + 1] = fmaxf(hi + bb[2 * j + 1], 0.f);
                acc[i][j] = 0ull;
            }
            *(float4*)&Atile[(rrow + i) * AS + ccol]     = make_float4(o[0], o[1], o[2], o[3]);
            *(float4*)&Atile[(rrow + i) * AS + ccol + 4] = make_float4(o[4], o[5], o[6], o[7]);
        }
    }
    CONS_BAR();

    gemm_from_atile(Atile, Wb, Ws, tid, rrow, ccol, acc);

    {   // epilogue2
        float4 bv0 = __ldg((const float4*)(bbv + ccol));
        float4 bv1 = __ldg((const float4*)(bbv + ccol + 4));
        float bb[8] = {bv0.x, bv0.y, bv0.z, bv0.w, bv1.x, bv1.y, bv1.z, bv1.w};
#pragma unroll
        for (int i = 0; i < 8; i++) {
            int grow = row0 + rrow + i;
            if (grow < N) {
                float o[8];
#pragma unroll
                for (int j = 0; j < 4; j++) {
                    float lo, hi;
                    asm("mov.b64 {%0, %1}, %2;" : "=f"(lo), "=f"(hi) : "l"(acc[i][j]));
                    o[2 * j]     = lo + bb[2 * j];
                    o[2 * j + 1] = hi + bb[2 * j + 1];
                }
                if (mode == 0) {
                    *(float4*)(OUT + (size_t)grow * 128 + ccol)     = make_float4(o[0], o[1], o[2], o[3]);
                    *(float4*)(OUT + (size_t)grow * 128 + ccol + 4) = make_float4(o[4], o[5], o[6], o[7]);
                } else {
                    int g = __ldg(batch + grow);
                    float* p = pool + (size_t)g * 128 + ccol;
                    asm volatile("red.global.add.v4.f32 [%0], {%1, %2, %3, %4};"
                                 :: "l"(p), "f"(o[0]), "f"(o[1]), "f"(o[2]), "f"(o[3]) : "memory");
                    asm volatile("red.global.add.v4.f32 [%0], {%1, %2, %3, %4};"
                                 :: "l"(p + 4), "f"(o[4]), "f"(o[5]), "f"(o[6]), "f"(o[7]) : "memory");
                }
            }
        }
    }
}

__global__ __launch_bounds__(512, 1)
void fused_layer_kernel(const float* __restrict__ X,
                        const int* __restrict__ adj, const int* __restrict__ off,
                        const float* __restrict__ Wa, const float* __restrict__ ba,
                        const float* __restrict__ Wb, const float* __restrict__ bbv,
                        float* __restrict__ OUT,
                        const int* __restrict__ batch, float* __restrict__ pool,
                        int* __restrict__ tctr,
                        int N, int mode) {
    extern __shared__ float sm[];
    float* Abuf0 = sm;
    float* Abuf1 = sm + TROWS * AS;
    float* Ws    = sm + 2 * TROWS * AS;
    int*   tiles = (int*)(sm + 2 * TROWS * AS + 2 * TK * 128);  // 2 slots

    const int tid = threadIdx.x, wid = tid >> 5, lane = tid & 31;
    const int ntiles = (N + TROWS - 1) / TROWS;   // 391

    // consumer geometry (tid 0..255)
    const int tx = tid & 15, ty = (tid & 255) >> 4;
    const int rrow = ty * 8, ccol = tx * 8;

    // ---- prologue: pop tile 0, all 16 warps gather it ----
    if (tid == 0) tiles[0] = atomicAdd(tctr + mode, 1);
    __syncthreads();
    int t0 = tiles[0];
    if (t0 < ntiles)
        gather_rows(X, adj, off, Abuf0, t0 * TROWS, N, wid, 16, lane);
    __syncthreads();

    for (int i = 0; ; i++) {
        int t = tiles[i & 1];
        if (t >= ntiles) break;
        float* Ab = (i & 1) ? Abuf1 : Abuf0;
        if (tid < NCONS) {
            consumer_tile(Ab, Ws, Wa, ba, Wb, bbv, OUT, batch, pool,
                          t * TROWS, N, mode, tid, rrow, ccol);
        } else {
            // pop next tile (one producer thread), broadcast to producer warps
            if (tid == NCONS) tiles[(i + 1) & 1] = atomicAdd(tctr + mode, 1);
            PROD_BAR();
            int tn = tiles[(i + 1) & 1];
            if (tn < ntiles) {
                float* An = (i & 1) ? Abuf0 : Abuf1;
                gather_rows(X, adj, off, An, tn * TROWS, N, wid - 8, 8, lane);
            }
        }
        __syncthreads();
    }
}

// ---------------- head: out = (sums/cnt) @ Wl + bl --------------------------
__global__ void final_kernel(const float* __restrict__ sums, const float* __restrict__ cnt,
                             const float* __restrict__ Wl, const float* __restrict__ bl,
                             float* __restrict__ out) {
    int g = blockIdx.x;
    int o = threadIdx.x;  // 64 threads
    __shared__ float p[128];
    float c = fmaxf(__ldg(cnt + g), 1.0f);
    for (int k = threadIdx.x; k < 128; k += 64)
        p[k] = __ldg(sums + g * 128 + k) / c;
    __syncthreads();
    float acc = __ldg(bl + o);
#pragma unroll 16
    for (int k = 0; k < 128; k++)
        acc += p[k] * __ldg(Wl + k * 64 + o);
    out[g * 64 + o] = acc;
}

// ---------------- launch -----------------------------------------------------
extern "C" void kernel_launch(void* const* d_in, const int* in_sizes, int n_in,
                              void* d_out, int out_size) {
    const float* x     = (const float*)d_in[0];
    const int*   ei    = (const int*)  d_in[1];
    const int*   batch = (const int*)  d_in[2];
    const float* W1a = (const float*)d_in[3];
    const float* b1a = (const float*)d_in[4];
    const float* W1b = (const float*)d_in[5];
    const float* b1b = (const float*)d_in[6];
    const float* W2a = (const float*)d_in[7];
    const float* b2a = (const float*)d_in[8];
    const float* W2b = (const float*)d_in[9];
    const float* b2b = (const float*)d_in[10];
    const float* Wl  = (const float*)d_in[11];
    const float* bl  = (const float*)d_in[12];
    float* out = (float*)d_out;

    const int N = in_sizes[0] / 128;
    const int E = in_sizes[1] / 2;
    const int* src = ei;
    const int* dst = ei + E;

    float *h, *pool;
    int *deg, *off, *cur, *adj, *tctr;
    cudaGetSymbolAddress((void**)&h,    g_h);
    cudaGetSymbolAddress((void**)&pool, g_pool);
    cudaGetSymbolAddress((void**)&deg,  g_deg);
    cudaGetSymbolAddress((void**)&off,  g_off);
    cudaGetSymbolAddress((void**)&cur,  g_cur);
    cudaGetSymbolAddress((void**)&adj,  g_adj);
    cudaGetSymbolAddress((void**)&tctr, g_tctr);
    float* cnt = pool + 256 * 128;

    cudaFuncSetAttribute(fused_layer_kernel,
                         cudaFuncAttributeMaxDynamicSharedMemorySize, SMEM_BYTES);

    const int eblocks = (E + 255) / 256;
    const int nblocks = (N + 255) / 256;

    // ---- CSR build (deg zero at entry; fill also resets deg + tile ctrs) ----
    count_kernel<<<eblocks, 256>>>(dst, deg, E);                       // #1
    scan_kernel <<<1, 1024>>>(deg, off, cur, N);                       // #2
    fill_kernel <<<eblocks, 256>>>(src, dst, cur, adj, deg, tctr, E);  // #3

    // ---- layer 1 (launch #4 — ncu capture target) ----
    fused_layer_kernel<<<NSM, 512, SMEM_BYTES>>>(
        x, adj, off, W1a, b1a, W1b, b1b, h, batch, pool, tctr, N, 0);

    // ---- pool/cnt init + counts ----
    zero_kernel<<<33, 256>>>(pool, (256 * 128 + 256) / 4);             // #5
    cnt_kernel <<<nblocks, 256>>>(batch, cnt, N);                      // #6

    // ---- layer 2: pool += MLP2(h + gather), fused ----
    fused_layer_kernel<<<NSM, 512, SMEM_BYTES>>>(
        h, adj, off, W2a, b2a, W2b, b2b, nullptr, batch, pool, tctr, N, 1);

    // ---- head ----
    final_kernel<<<256, 64>>>(pool, cnt, Wl, bl, out);
}